// round 8
// baseline (speedup 1.0000x reference)
#include <cuda_runtime.h>
#include <cuda_bf16.h>
#include <cstdint>

#define NODES  262144
#define H      256
#define NGRAPH 4096
#define NCHUNK 128

// ---- gemm tiling ----
#define TM   128
#define TN   128
#define BK   32
#define NKC  (H / BK)   // 8

// padded SMEM row: 32 halves + 8 pad = 80 B (conflict-free for LDSM)
#define ROWB     80
#define XS_HI    0
#define XS_LO    10240
#define WS_HI    20480
#define WS_LO    30720
#define STAGE    40960
// fp32 x staging: 128 rows x 144 B (128 data + 16 pad) = 18432 B
#define XSTG_ROWB 144
#define XSTG_OFF (2 * STAGE)              // 81920
#define SC_OFF   (XSTG_OFF + 18432)       // 100352
#define B1_OFF   (SC_OFF + 512)
#define W2_OFF   (B1_OFF + 512)
#define SMEM_TOTAL (W2_OFF + 512)         // 101888 B -> 2 CTAs/SM

// ---------------- scratch ----------------
__device__ float d_scores[NODES];
__device__ float d_cmax[NCHUNK];
__device__ float d_cdenom[NCHUNK];
__device__ int   d_gstart[NGRAPH + 1];
__device__ int   d_batch32[NODES];
__device__ __align__(16) __nv_bfloat16 d_W1T_hi[H * H];  // [n][k]
__device__ __align__(16) __nv_bfloat16 d_W1T_lo[H * H];  // [n][k]

// ---------------- helpers ----------------
__device__ __forceinline__ uint32_t smem_u32(const void* p) {
    uint32_t a;
    asm("{ .reg .u64 t; cvta.to.shared.u64 t, %1; cvt.u32.u64 %0, t; }"
        : "=r"(a) : "l"(p));
    return a;
}
__device__ __forceinline__ void cp_async16(uint32_t dst, const void* src) {
    asm volatile("cp.async.cg.shared.global [%0], [%1], 16;"
                 :: "r"(dst), "l"(src) : "memory");
}
__device__ __forceinline__ uint32_t bfpack(float a, float b) {
    __nv_bfloat162 t = __halves2bfloat162(__float2bfloat16(a), __float2bfloat16(b));
    return *reinterpret_cast<uint32_t*>(&t);
}
__device__ __forceinline__ float fast_tanh(float x) {
    float p = fminf(fmaxf(x, -15.f), 15.f);
    float e = __expf(2.f * p);
    return __fdividef(e - 1.f, e + 1.f);
}
__device__ __forceinline__ void ldsm4(uint32_t* r, uint32_t addr) {
    asm volatile("ldmatrix.sync.aligned.m8n8.x4.shared.b16 {%0,%1,%2,%3}, [%4];"
                 : "=r"(r[0]), "=r"(r[1]), "=r"(r[2]), "=r"(r[3]) : "r"(addr));
}
#define MMA_BF16(c, a0, a1, a2, a3, b0, b1)                                    \
    asm volatile(                                                              \
        "mma.sync.aligned.m16n8k16.row.col.f32.bf16.bf16.f32 "                 \
        "{%0,%1,%2,%3}, {%4,%5,%6,%7}, {%8,%9}, {%0,%1,%2,%3};"                \
        : "+f"(c[0]), "+f"(c[1]), "+f"(c[2]), "+f"(c[3])                       \
        : "r"(a0), "r"(a1), "r"(a2), "r"(a3), "r"(b0), "r"(b1))

// ---------------- W1 split + transpose ----------------
__global__ void prep_w_kernel(const float* __restrict__ W1)
{
    int k = blockIdx.x, n = threadIdx.x;
    float v = W1[k * H + n];
    __nv_bfloat16 hi = __float2bfloat16(v);
    d_W1T_hi[n * H + k] = hi;
    d_W1T_lo[n * H + k] = __float2bfloat16(v - __bfloat162float(hi));
}

// ---------------- batch -> int32, zero scores ----------------
__global__ void conv_batch_kernel(const void* __restrict__ batch)
{
    int i = blockIdx.x * blockDim.x + threadIdx.x;
    if (i >= NODES) return;
    const int* b32 = (const int*)batch;
    bool is64 = (b32[128] == 1);
    d_batch32[i] = is64 ? (int)((const long long*)batch)[i] : b32[i];
    d_scores[i] = 0.f;
}

__global__ void calc_gstart_kernel()
{
    int i = blockIdx.x * blockDim.x + threadIdx.x;
    if (i >= NODES) return;
    int b = d_batch32[i];
    if (i == 0) {
        for (int g = 0; g <= b; ++g) d_gstart[g] = 0;
    } else {
        int pb = d_batch32[i - 1];
        for (int g = pb + 1; g <= b; ++g) d_gstart[g] = i;
    }
    if (i == NODES - 1)
        for (int g = b + 1; g <= NGRAPH; ++g) d_gstart[g] = NODES;
}

// ---------------- pipelined HMMA GEMM -> tanh -> dot(W2) -> scores ----------------
extern __shared__ __align__(16) char smem[];

__global__ void __launch_bounds__(256, 2) gemm_scores_kernel(
    const float* __restrict__ x, const float* __restrict__ b1,
    const float* __restrict__ W2)
{
    const int tid = threadIdx.x;
    const int warp = tid >> 5, lane = tid & 31;
    const int g = lane >> 2, t = lane & 3;
    const int warp_m = warp & 1;
    const int warp_n = warp >> 1;
    const int row0 = (blockIdx.x >> 1) * TM;
    const int cb   = blockIdx.x & 1;
    const int col_base = cb * TN;

    float* score_s = (float*)(smem + SC_OFF);
    float* b1s     = (float*)(smem + B1_OFF);
    float* w2s     = (float*)(smem + W2_OFF);
    const uint32_t sb = smem_u32(smem);

    if (tid < 128) {
        score_s[tid] = 0.f;
        b1s[tid] = b1[col_base + tid];
        w2s[tid] = W2[col_base + tid];
    }

    const int r  = tid >> 1;   // tile row 0..127
    const int hf = tid & 1;    // 16-float half of BK=32

    // per-thread staging region (cp.async dst == split-read src)
    const uint32_t xstg_off = XSTG_OFF + (uint32_t)r * XSTG_ROWB + (uint32_t)hf * 64;
    // bf16 store offset
    const uint32_t doff = (uint32_t)r * ROWB + (uint32_t)hf * 32;
    // W global row base
    const __nv_bfloat16* gWh = d_W1T_hi + (size_t)(col_base + r) * H + hf * 16;
    const __nv_bfloat16* gWl = d_W1T_lo + (size_t)(col_base + r) * H + hf * 16;
    const float* gx = x + (size_t)(row0 + r) * H + hf * 16;

    // ldmatrix addressing
    const uint32_t lrow  = lane & 15;
    const uint32_t lhalf = (lane >> 4) * 16;
    uint32_t aBase[4], bBase[2];
#pragma unroll
    for (int mf = 0; mf < 4; ++mf)
        aBase[mf] = (uint32_t)(warp_m * 64 + mf * 16 + lrow) * ROWB + lhalf;
#pragma unroll
    for (int p = 0; p < 2; ++p)
        bBase[p] = (uint32_t)(warp_n * 32 + p * 16 + lrow) * ROWB + lhalf;

    float acc[4][4][4];
#pragma unroll
    for (int a = 0; a < 4; ++a)
#pragma unroll
        for (int b = 0; b < 4; ++b)
#pragma unroll
            for (int c = 0; c < 4; ++c) acc[a][b][c] = 0.f;

    // ---- prologue ----
    // G0: x(0) -> xstg, W(0) -> stage0
    {
#pragma unroll
        for (int j = 0; j < 4; ++j)
            cp_async16(sb + xstg_off + j * 16, gx + j * 4);
        cp_async16(sb + WS_HI + doff,      gWh);
        cp_async16(sb + WS_HI + doff + 16, gWh + 8);
        cp_async16(sb + WS_LO + doff,      gWl);
        cp_async16(sb + WS_LO + doff + 16, gWl + 8);
        asm volatile("cp.async.commit_group;" ::: "memory");
        asm volatile("cp.async.wait_group 0;" ::: "memory");
    }
    __syncthreads();
    // split x(0) -> XS stage0 ; issue G1: x(1)->xstg, W(1)->stage1
    {
        const float4* xr = (const float4*)(smem + xstg_off);
        float4 v0 = xr[0], v1 = xr[1], v2 = xr[2], v3 = xr[3];
        float f[16] = {v0.x, v0.y, v0.z, v0.w, v1.x, v1.y, v1.z, v1.w,
                       v2.x, v2.y, v2.z, v2.w, v3.x, v3.y, v3.z, v3.w};
        uint32_t hi[8], lo[8];
#pragma unroll
        for (int i = 0; i < 8; ++i) {
            float a = f[2 * i], b = f[2 * i + 1];
            hi[i] = bfpack(a, b);
            lo[i] = bfpack(a - __bfloat162float(__float2bfloat16(a)),
                           b - __bfloat162float(__float2bfloat16(b)));
        }
        *(uint4*)(smem + XS_HI + doff)      = make_uint4(hi[0], hi[1], hi[2], hi[3]);
        *(uint4*)(smem + XS_HI + doff + 16) = make_uint4(hi[4], hi[5], hi[6], hi[7]);
        *(uint4*)(smem + XS_LO + doff)      = make_uint4(lo[0], lo[1], lo[2], lo[3]);
        *(uint4*)(smem + XS_LO + doff + 16) = make_uint4(lo[4], lo[5], lo[6], lo[7]);

#pragma unroll
        for (int j = 0; j < 4; ++j)
            cp_async16(sb + xstg_off + j * 16, gx + BK + j * 4);
        cp_async16(sb + STAGE + WS_HI + doff,      gWh + BK);
        cp_async16(sb + STAGE + WS_HI + doff + 16, gWh + BK + 8);
        cp_async16(sb + STAGE + WS_LO + doff,      gWl + BK);
        cp_async16(sb + STAGE + WS_LO + doff + 16, gWl + BK + 8);
        asm volatile("cp.async.commit_group;" ::: "memory");
    }
    __syncthreads();

    // ---- main loop ----
    for (int s = 0; s < NKC; ++s) {
        const uint32_t sc = sb + (uint32_t)(s & 1) * STAGE;

        // MMAs over stage s
#pragma unroll
        for (int ks = 0; ks < 2; ++ks) {
            const uint32_t ko = (uint32_t)ks * 32;
            uint32_t BH[2][4], BL[2][4];
            ldsm4(BH[0], sc + WS_HI + bBase[0] + ko);
            ldsm4(BH[1], sc + WS_HI + bBase[1] + ko);
            ldsm4(BL[0], sc + WS_LO + bBase[0] + ko);
            ldsm4(BL[1], sc + WS_LO + bBase[1] + ko);
#pragma unroll
            for (int mf = 0; mf < 4; ++mf) {
                uint32_t AH[4], AL[4];
                ldsm4(AH, sc + XS_HI + aBase[mf] + ko);
                ldsm4(AL, sc + XS_LO + aBase[mf] + ko);
#pragma unroll
                for (int nf = 0; nf < 4; ++nf)
                    MMA_BF16(acc[mf][nf], AH[0], AH[1], AH[2], AH[3],
                             BH[nf >> 1][nf & 1], BH[nf >> 1][(nf & 1) + 2]);
#pragma unroll
                for (int nf = 0; nf < 4; ++nf)
                    MMA_BF16(acc[mf][nf], AH[0], AH[1], AH[2], AH[3],
                             BL[nf >> 1][nf & 1], BL[nf >> 1][(nf & 1) + 2]);
#pragma unroll
                for (int nf = 0; nf < 4; ++nf)
                    MMA_BF16(acc[mf][nf], AL[0], AL[1], AL[2], AL[3],
                             BH[nf >> 1][nf & 1], BH[nf >> 1][(nf & 1) + 2]);
            }
        }

        if (s < NKC - 1) {
            // stage s+1 data (x in xstg, W in its stage buffer) has arrived
            asm volatile("cp.async.wait_group 0;" ::: "memory");
            __syncthreads();   // all warps done reading stage s & s-1 buffers

            // split x(s+1) from staging into XS of stage (s+1)&1
            char* stgn = smem + ((s + 1) & 1) * STAGE;
            const float4* xr = (const float4*)(smem + xstg_off);
            float4 v0 = xr[0], v1 = xr[1], v2 = xr[2], v3 = xr[3];
            float f[16] = {v0.x, v0.y, v0.z, v0.w, v1.x, v1.y, v1.z, v1.w,
                           v2.x, v2.y, v2.z, v2.w, v3.x, v3.y, v3.z, v3.w};
            uint32_t hi[8], lo[8];
#pragma unroll
            for (int i = 0; i < 8; ++i) {
                float a = f[2 * i], b = f[2 * i + 1];
                hi[i] = bfpack(a, b);
                lo[i] = bfpack(a - __bfloat162float(__float2bfloat16(a)),
                               b - __bfloat162float(__float2bfloat16(b)));
            }
            *(uint4*)(stgn + XS_HI + doff)      = make_uint4(hi[0], hi[1], hi[2], hi[3]);
            *(uint4*)(stgn + XS_HI + doff + 16) = make_uint4(hi[4], hi[5], hi[6], hi[7]);
            *(uint4*)(stgn + XS_LO + doff)      = make_uint4(lo[0], lo[1], lo[2], lo[3]);
            *(uint4*)(stgn + XS_LO + doff + 16) = make_uint4(lo[4], lo[5], lo[6], lo[7]);

            // issue stage s+2 (x into own staging region, W into stage (s)&1)
            if (s + 2 < NKC) {
                const int k2 = (s + 2) * BK;
                const uint32_t wdst = sb + (uint32_t)(s & 1) * STAGE;
#pragma unroll
                for (int j = 0; j < 4; ++j)
                    cp_async16(sb + xstg_off + j * 16, gx + k2 + j * 4);
                cp_async16(wdst + WS_HI + doff,      gWh + k2);
                cp_async16(wdst + WS_HI + doff + 16, gWh + k2 + 8);
                cp_async16(wdst + WS_LO + doff,      gWl + k2);
                cp_async16(wdst + WS_LO + doff + 16, gWl + k2 + 8);
            }
            asm volatile("cp.async.commit_group;" ::: "memory");
            __syncthreads();   // split stores visible before MMA(s+1)
        }
    }

    // ---- epilogue ----
    float partA[4] = {0.f, 0.f, 0.f, 0.f};
    float partB[4] = {0.f, 0.f, 0.f, 0.f};
#pragma unroll
    for (int mf = 0; mf < 4; ++mf) {
#pragma unroll
        for (int nf = 0; nf < 4; ++nf) {
            const int c0 = warp_n * 32 + nf * 8 + 2 * t;
            const float w20 = w2s[c0], w21 = w2s[c0 + 1];
            const float bb0 = b1s[c0], bb1 = b1s[c0 + 1];
            partA[mf] += fast_tanh(acc[mf][nf][0] + bb0) * w20
                       + fast_tanh(acc[mf][nf][1] + bb1) * w21;
            partB[mf] += fast_tanh(acc[mf][nf][2] + bb0) * w20
                       + fast_tanh(acc[mf][nf][3] + bb1) * w21;
        }
    }
#pragma unroll
    for (int mf = 0; mf < 4; ++mf) {
        partA[mf] += __shfl_xor_sync(0xffffffffu, partA[mf], 1);
        partA[mf] += __shfl_xor_sync(0xffffffffu, partA[mf], 2);
        partB[mf] += __shfl_xor_sync(0xffffffffu, partB[mf], 1);
        partB[mf] += __shfl_xor_sync(0xffffffffu, partB[mf], 2);
    }
    if (t == 0) {
#pragma unroll
        for (int mf = 0; mf < 4; ++mf) {
            atomicAdd(&score_s[warp_m * 64 + mf * 16 + g], partA[mf]);
            atomicAdd(&score_s[warp_m * 64 + mf * 16 + g + 8], partB[mf]);
        }
    }
    __syncthreads();
    if (tid < 128) atomicAdd(&d_scores[row0 + tid], score_s[tid]);
}

// ---------------- per-chunk max + exp-sum ----------------
__global__ void chunk_stats_kernel()
{
    const int c = blockIdx.x;
    const int s = d_gstart[c * 32];
    const int e = d_gstart[c * 32 + 32];
    const int tid = threadIdx.x;

    __shared__ float red[8];
    float m = -3.4e38f;
    for (int i = s + tid; i < e; i += 256) m = fmaxf(m, d_scores[i]);
#pragma unroll
    for (int o = 16; o; o >>= 1) m = fmaxf(m, __shfl_xor_sync(0xffffffffu, m, o));
    if ((tid & 31) == 0) red[tid >> 5] = m;
    __syncthreads();
    if (tid == 0) {
        float mm = red[0];
        for (int j = 1; j < 8; ++j) mm = fmaxf(mm, red[j]);
        red[0] = mm;
    }
    __syncthreads();
    const float bm = red[0];
    __syncthreads();

    float sum = 0.f;
    for (int i = s + tid; i < e; i += 256) sum += expf(d_scores[i] - bm);
#pragma unroll
    for (int o = 16; o; o >>= 1) sum += __shfl_xor_sync(0xffffffffu, sum, o);
    if ((tid & 31) == 0) red[tid >> 5] = sum;
    __syncthreads();
    if (tid == 0) {
        float ss = 0.f;
        for (int j = 0; j < 8; ++j) ss += red[j];
        d_cmax[c] = bm;
        d_cdenom[c] = ss;
    }
}

// ---------------- weighted pooling ----------------
__global__ void pool_kernel(const float* __restrict__ x, float* __restrict__ out)
{
    const int gph = blockIdx.x;
    const int s = d_gstart[gph], e = d_gstart[gph + 1];
    const int c = gph >> 5;
    const float m = d_cmax[c];
    const float invd = (e > s) ? 1.f / d_cdenom[c] : 0.f;
    const int t = threadIdx.x;

    __shared__ float sw[256];
    float acc = 0.f;
    for (int base = s; base < e; base += 256) {
        const int cnt = min(256, e - base);
        if (t < cnt) sw[t] = expf(d_scores[base + t] - m) * invd;
        __syncthreads();
#pragma unroll 8
        for (int j = 0; j < cnt; ++j)
            acc += sw[j] * x[(size_t)(base + j) * H + t];
        __syncthreads();
    }
    out[(size_t)gph * H + t] = acc;
}

// ---------------- launch ----------------
extern "C" void kernel_launch(void* const* d_in, const int* in_sizes, int n_in,
                              void* d_out, int out_size)
{
    const float* x     = (const float*)d_in[0];
    const void*  batch = d_in[1];
    const float* W1    = (const float*)d_in[2];
    const float* b1    = (const float*)d_in[3];
    const float* W2    = (const float*)d_in[4];
    float* out = (float*)d_out;

    cudaFuncSetAttribute(gemm_scores_kernel,
                         cudaFuncAttributeMaxDynamicSharedMemorySize, SMEM_TOTAL);

    prep_w_kernel<<<H, H>>>(W1);
    conv_batch_kernel<<<NODES / 256, 256>>>(batch);
    calc_gstart_kernel<<<NODES / 256, 256>>>();
    gemm_scores_kernel<<<(NODES / TM) * 2, 256, SMEM_TOTAL>>>(x, b1, W2);
    chunk_stats_kernel<<<NCHUNK, 256>>>();
    pool_kernel<<<NGRAPH, 256>>>(x, out);
}

// round 9
// speedup vs baseline: 1.1708x; 1.1708x over previous
#include <cuda_runtime.h>
#include <cuda_bf16.h>
#include <cstdint>

#define NODES  262144
#define H      256
#define NGRAPH 4096
#define NCHUNK 128

// ---- gemm tiling ----
#define TM   128
#define TN   128
#define BK   32
#define NKC  (H / BK)

// padded SMEM row: 32 halves + 8 pad = 80 B (conflict-free for LDSM)
#define ROWB     80
#define XS_HI    0
#define XS_LO    10240
#define WS_HI    20480
#define WS_LO    30720
#define STAGE    40960
#define SC_OFF   (2 * STAGE)
#define B1_OFF   (SC_OFF + 512)
#define W2_OFF   (B1_OFF + 512)
#define SMEM_TOTAL (W2_OFF + 512)     // 83456 B -> 2 CTAs/SM

// ---------------- scratch ----------------
__device__ float d_scores[NODES];
__device__ float d_cmax[NCHUNK];
__device__ float d_cdenom[NCHUNK];
__device__ int   d_gstart[NGRAPH + 1];
__device__ int   d_batch32[NODES];
__device__ __align__(16) __nv_bfloat16 d_W1T_hi[H * H];  // [n][k]
__device__ __align__(16) __nv_bfloat16 d_W1T_lo[H * H];  // [n][k]

// ---------------- helpers ----------------
__device__ __forceinline__ uint32_t smem_u32(const void* p) {
    uint32_t a;
    asm("{ .reg .u64 t; cvta.to.shared.u64 t, %1; cvt.u32.u64 %0, t; }"
        : "=r"(a) : "l"(p));
    return a;
}
__device__ __forceinline__ void cp_async16(uint32_t dst, const void* src) {
    asm volatile("cp.async.cg.shared.global [%0], [%1], 16;"
                 :: "r"(dst), "l"(src) : "memory");
}
// fast split: hi = rn-bf16 pair (1 cvt), residual via bit-masked hi floats
__device__ __forceinline__ void split2(float a, float b, uint32_t& hi, uint32_t& lo) {
    asm("cvt.rn.bf16x2.f32 %0, %1, %2;" : "=r"(hi) : "f"(b), "f"(a));
    float ha = __uint_as_float(hi << 16);
    float hb = __uint_as_float(hi & 0xFFFF0000u);
    float ra = a - ha, rb = b - hb;
    asm("cvt.rn.bf16x2.f32 %0, %1, %2;" : "=r"(lo) : "f"(rb), "f"(ra));
}
__device__ __forceinline__ float fast_tanh(float x) {
    float p = fminf(fmaxf(x, -15.f), 15.f);
    float e = __expf(2.f * p);
    return __fdividef(e - 1.f, e + 1.f);
}
__device__ __forceinline__ void ldsm4(uint32_t* r, uint32_t addr) {
    asm volatile("ldmatrix.sync.aligned.m8n8.x4.shared.b16 {%0,%1,%2,%3}, [%4];"
                 : "=r"(r[0]), "=r"(r[1]), "=r"(r[2]), "=r"(r[3]) : "r"(addr));
}
#define MMA_BF16(c, a0, a1, a2, a3, b0, b1)                                    \
    asm volatile(                                                              \
        "mma.sync.aligned.m16n8k16.row.col.f32.bf16.bf16.f32 "                 \
        "{%0,%1,%2,%3}, {%4,%5,%6,%7}, {%8,%9}, {%0,%1,%2,%3};"                \
        : "+f"(c[0]), "+f"(c[1]), "+f"(c[2]), "+f"(c[3])                       \
        : "r"(a0), "r"(a1), "r"(a2), "r"(a3), "r"(b0), "r"(b1))

// ---------------- W1 split + transpose ----------------
__global__ void prep_w_kernel(const float* __restrict__ W1)
{
    int k = blockIdx.x, n = threadIdx.x;
    float v = W1[k * H + n];
    __nv_bfloat16 hi = __float2bfloat16(v);
    d_W1T_hi[n * H + k] = hi;
    d_W1T_lo[n * H + k] = __float2bfloat16(v - __bfloat162float(hi));
}

// ---------------- batch -> int32, zero scores ----------------
__global__ void conv_batch_kernel(const void* __restrict__ batch)
{
    int i = blockIdx.x * blockDim.x + threadIdx.x;
    if (i >= NODES) return;
    const int* b32 = (const int*)batch;
    bool is64 = (b32[128] == 1);
    d_batch32[i] = is64 ? (int)((const long long*)batch)[i] : b32[i];
    d_scores[i] = 0.f;
}

__global__ void calc_gstart_kernel()
{
    int i = blockIdx.x * blockDim.x + threadIdx.x;
    if (i >= NODES) return;
    int b = d_batch32[i];
    if (i == 0) {
        for (int g = 0; g <= b; ++g) d_gstart[g] = 0;
    } else {
        int pb = d_batch32[i - 1];
        for (int g = pb + 1; g <= b; ++g) d_gstart[g] = i;
    }
    if (i == NODES - 1)
        for (int g = b + 1; g <= NGRAPH; ++g) d_gstart[g] = NODES;
}

// ---------------- pipelined HMMA GEMM -> tanh -> dot(W2) -> scores ----------------
extern __shared__ __align__(16) char smem[];

__global__ void __launch_bounds__(256, 2) gemm_scores_kernel(
    const float* __restrict__ x, const float* __restrict__ b1,
    const float* __restrict__ W2)
{
    const int tid = threadIdx.x;
    const int warp = tid >> 5, lane = tid & 31;
    const int g = lane >> 2, t = lane & 3;
    const int warp_m = warp & 1;
    const int warp_n = warp >> 1;
    const int row0 = (blockIdx.x >> 1) * TM;
    const int cb   = blockIdx.x & 1;
    const int col_base = cb * TN;

    float* score_s = (float*)(smem + SC_OFF);
    float* b1s     = (float*)(smem + B1_OFF);
    float* w2s     = (float*)(smem + W2_OFF);
    const uint32_t sb = smem_u32(smem);

    if (tid < 128) {
        score_s[tid] = 0.f;
        b1s[tid] = b1[col_base + tid];
        w2s[tid] = W2[col_base + tid];
    }

    const int r  = tid >> 1;
    const int hf = tid & 1;

    const uint32_t lrow  = lane & 15;
    const uint32_t lhalf = (lane >> 4) * 16;
    uint32_t aBase[4], bBase[2];
#pragma unroll
    for (int mf = 0; mf < 4; ++mf)
        aBase[mf] = (uint32_t)(warp_m * 64 + mf * 16 + lrow) * ROWB + lhalf;
#pragma unroll
    for (int p = 0; p < 2; ++p)
        bBase[p] = (uint32_t)(warp_n * 32 + p * 16 + lrow) * ROWB + lhalf;

    float acc[4][4][4];
#pragma unroll
    for (int a = 0; a < 4; ++a)
#pragma unroll
        for (int b = 0; b < 4; ++b)
#pragma unroll
            for (int c = 0; c < 4; ++c) acc[a][b][c] = 0.f;

    // ---- prologue: fill stage 0 ----
    {
        const float4* ap = (const float4*)(x + (size_t)(row0 + r) * H + hf * 16);
        float4 av[4];
#pragma unroll
        for (int j = 0; j < 4; ++j) av[j] = ap[j];

        char* stg = smem;
        uint32_t hi[8], lo[8];
#pragma unroll
        for (int j = 0; j < 4; ++j) {
            split2(av[j].x, av[j].y, hi[2 * j],     lo[2 * j]);
            split2(av[j].z, av[j].w, hi[2 * j + 1], lo[2 * j + 1]);
        }
        uint32_t doff = (uint32_t)r * ROWB + (uint32_t)hf * 32;
        *(uint4*)(stg + XS_HI + doff)      = make_uint4(hi[0], hi[1], hi[2], hi[3]);
        *(uint4*)(stg + XS_HI + doff + 16) = make_uint4(hi[4], hi[5], hi[6], hi[7]);
        *(uint4*)(stg + XS_LO + doff)      = make_uint4(lo[0], lo[1], lo[2], lo[3]);
        *(uint4*)(stg + XS_LO + doff + 16) = make_uint4(lo[4], lo[5], lo[6], lo[7]);

        const __nv_bfloat16* gh = d_W1T_hi + (size_t)(col_base + r) * H + hf * 16;
        const __nv_bfloat16* gl = d_W1T_lo + (size_t)(col_base + r) * H + hf * 16;
        cp_async16(sb + WS_HI + doff,      gh);
        cp_async16(sb + WS_HI + doff + 16, gh + 8);
        cp_async16(sb + WS_LO + doff,      gl);
        cp_async16(sb + WS_LO + doff + 16, gl + 8);
        asm volatile("cp.async.commit_group;" ::: "memory");
        asm volatile("cp.async.wait_group 0;" ::: "memory");
    }
    __syncthreads();

    // ---- main loop (fully unrolled: stage offsets become immediates) ----
#pragma unroll
    for (int kc = 0; kc < NKC; ++kc) {
        const int cur = kc & 1;
        const int nxt = cur ^ 1;
        const bool has_next = (kc + 1) < NKC;
        const uint32_t sc = sb + cur * STAGE;
        float4 av[4];

        if (has_next) {
            const int k1 = (kc + 1) * BK;
            const float4* ap =
                (const float4*)(x + (size_t)(row0 + r) * H + k1 + hf * 16);
#pragma unroll
            for (int j = 0; j < 4; ++j) av[j] = ap[j];
            uint32_t doff = (uint32_t)r * ROWB + (uint32_t)hf * 32;
            const uint32_t dst = sb + nxt * STAGE;
            const __nv_bfloat16* gh = d_W1T_hi + (size_t)(col_base + r) * H + k1 + hf * 16;
            const __nv_bfloat16* gl = d_W1T_lo + (size_t)(col_base + r) * H + k1 + hf * 16;
            cp_async16(dst + WS_HI + doff,      gh);
            cp_async16(dst + WS_HI + doff + 16, gh + 8);
            cp_async16(dst + WS_LO + doff,      gl);
            cp_async16(dst + WS_LO + doff + 16, gl + 8);
            asm volatile("cp.async.commit_group;" ::: "memory");
        }

#pragma unroll
        for (int ks = 0; ks < 2; ++ks) {
            const uint32_t ko = (uint32_t)ks * 32;
            uint32_t BH[2][4], BL[2][4];
            ldsm4(BH[0], sc + WS_HI + bBase[0] + ko);
            ldsm4(BH[1], sc + WS_HI + bBase[1] + ko);
            ldsm4(BL[0], sc + WS_LO + bBase[0] + ko);
            ldsm4(BL[1], sc + WS_LO + bBase[1] + ko);
#pragma unroll
            for (int mf = 0; mf < 4; ++mf) {
                uint32_t AH[4], AL[4];
                ldsm4(AH, sc + XS_HI + aBase[mf] + ko);
                ldsm4(AL, sc + XS_LO + aBase[mf] + ko);
#pragma unroll
                for (int nf = 0; nf < 4; ++nf)
                    MMA_BF16(acc[mf][nf], AH[0], AH[1], AH[2], AH[3],
                             BH[nf >> 1][nf & 1], BH[nf >> 1][(nf & 1) + 2]);
#pragma unroll
                for (int nf = 0; nf < 4; ++nf)
                    MMA_BF16(acc[mf][nf], AH[0], AH[1], AH[2], AH[3],
                             BL[nf >> 1][nf & 1], BL[nf >> 1][(nf & 1) + 2]);
#pragma unroll
                for (int nf = 0; nf < 4; ++nf)
                    MMA_BF16(acc[mf][nf], AL[0], AL[1], AL[2], AL[3],
                             BH[nf >> 1][nf & 1], BH[nf >> 1][(nf & 1) + 2]);
            }
        }

        if (has_next) {
            char* stgn = smem + nxt * STAGE;
            uint32_t hi[8], lo[8];
#pragma unroll
            for (int j = 0; j < 4; ++j) {
                split2(av[j].x, av[j].y, hi[2 * j],     lo[2 * j]);
                split2(av[j].z, av[j].w, hi[2 * j + 1], lo[2 * j + 1]);
            }
            uint32_t doff = (uint32_t)r * ROWB + (uint32_t)hf * 32;
            *(uint4*)(stgn + XS_HI + doff)      = make_uint4(hi[0], hi[1], hi[2], hi[3]);
            *(uint4*)(stgn + XS_HI + doff + 16) = make_uint4(hi[4], hi[5], hi[6], hi[7]);
            *(uint4*)(stgn + XS_LO + doff)      = make_uint4(lo[0], lo[1], lo[2], lo[3]);
            *(uint4*)(stgn + XS_LO + doff + 16) = make_uint4(lo[4], lo[5], lo[6], lo[7]);
            asm volatile("cp.async.wait_group 0;" ::: "memory");
        }
        __syncthreads();
    }

    // ---- epilogue ----
    float partA[4] = {0.f, 0.f, 0.f, 0.f};
    float partB[4] = {0.f, 0.f, 0.f, 0.f};
#pragma unroll
    for (int mf = 0; mf < 4; ++mf) {
#pragma unroll
        for (int nf = 0; nf < 4; ++nf) {
            const int c0 = warp_n * 32 + nf * 8 + 2 * t;
            const float w20 = w2s[c0], w21 = w2s[c0 + 1];
            const float bb0 = b1s[c0], bb1 = b1s[c0 + 1];
            partA[mf] += fast_tanh(acc[mf][nf][0] + bb0) * w20
                       + fast_tanh(acc[mf][nf][1] + bb1) * w21;
            partB[mf] += fast_tanh(acc[mf][nf][2] + bb0) * w20
                       + fast_tanh(acc[mf][nf][3] + bb1) * w21;
        }
    }
#pragma unroll
    for (int mf = 0; mf < 4; ++mf) {
        partA[mf] += __shfl_xor_sync(0xffffffffu, partA[mf], 1);
        partA[mf] += __shfl_xor_sync(0xffffffffu, partA[mf], 2);
        partB[mf] += __shfl_xor_sync(0xffffffffu, partB[mf], 1);
        partB[mf] += __shfl_xor_sync(0xffffffffu, partB[mf], 2);
    }
    if (t == 0) {
#pragma unroll
        for (int mf = 0; mf < 4; ++mf) {
            atomicAdd(&score_s[warp_m * 64 + mf * 16 + g], partA[mf]);
            atomicAdd(&score_s[warp_m * 64 + mf * 16 + g + 8], partB[mf]);
        }
    }
    __syncthreads();
    if (tid < 128) atomicAdd(&d_scores[row0 + tid], score_s[tid]);
}

// ---------------- per-chunk max + exp-sum ----------------
__global__ void chunk_stats_kernel()
{
    const int c = blockIdx.x;
    const int s = d_gstart[c * 32];
    const int e = d_gstart[c * 32 + 32];
    const int tid = threadIdx.x;

    __shared__ float red[8];
    float m = -3.4e38f;
    for (int i = s + tid; i < e; i += 256) m = fmaxf(m, d_scores[i]);
#pragma unroll
    for (int o = 16; o; o >>= 1) m = fmaxf(m, __shfl_xor_sync(0xffffffffu, m, o));
    if ((tid & 31) == 0) red[tid >> 5] = m;
    __syncthreads();
    if (tid == 0) {
        float mm = red[0];
        for (int j = 1; j < 8; ++j) mm = fmaxf(mm, red[j]);
        red[0] = mm;
    }
    __syncthreads();
    const float bm = red[0];
    __syncthreads();

    float sum = 0.f;
    for (int i = s + tid; i < e; i += 256) sum += expf(d_scores[i] - bm);
#pragma unroll
    for (int o = 16; o; o >>= 1) sum += __shfl_xor_sync(0xffffffffu, sum, o);
    if ((tid & 31) == 0) red[tid >> 5] = sum;
    __syncthreads();
    if (tid == 0) {
        float ss = 0.f;
        for (int j = 0; j < 8; ++j) ss += red[j];
        d_cmax[c] = bm;
        d_cdenom[c] = ss;
    }
}

// ---------------- weighted pooling ----------------
__global__ void pool_kernel(const float* __restrict__ x, float* __restrict__ out)
{
    const int gph = blockIdx.x;
    const int s = d_gstart[gph], e = d_gstart[gph + 1];
    const int c = gph >> 5;
    const float m = d_cmax[c];
    const float invd = (e > s) ? 1.f / d_cdenom[c] : 0.f;
    const int t = threadIdx.x;

    __shared__ float sw[256];
    float acc = 0.f;
    for (int base = s; base < e; base += 256) {
        const int cnt = min(256, e - base);
        if (t < cnt) sw[t] = expf(d_scores[base + t] - m) * invd;
        __syncthreads();
#pragma unroll 8
        for (int j = 0; j < cnt; ++j)
            acc += sw[j] * x[(size_t)(base + j) * H + t];
        __syncthreads();
    }
    out[(size_t)gph * H + t] = acc;
}

// ---------------- launch ----------------
extern "C" void kernel_launch(void* const* d_in, const int* in_sizes, int n_in,
                              void* d_out, int out_size)
{
    const float* x     = (const float*)d_in[0];
    const void*  batch = d_in[1];
    const float* W1    = (const float*)d_in[2];
    const float* b1    = (const float*)d_in[3];
    const float* W2    = (const float*)d_in[4];
    float* out = (float*)d_out;

    cudaFuncSetAttribute(gemm_scores_kernel,
                         cudaFuncAttributeMaxDynamicSharedMemorySize, SMEM_TOTAL);

    prep_w_kernel<<<H, H>>>(W1);
    conv_batch_kernel<<<NODES / 256, 256>>>(batch);
    calc_gstart_kernel<<<NODES / 256, 256>>>();
    gemm_scores_kernel<<<(NODES / TM) * 2, 256, SMEM_TOTAL>>>(x, b1, W2);
    chunk_stats_kernel<<<NCHUNK, 256>>>();
    pool_kernel<<<NGRAPH, 256>>>(x, out);
}

// round 10
// speedup vs baseline: 1.4921x; 1.2743x over previous
#include <cuda_runtime.h>
#include <cuda_fp16.h>
#include <cstdint>

#define NODES  262144
#define H      256
#define NGRAPH 4096
#define NCHUNK 128

// ---- gemm tiling ----
#define TM   128
#define TN   128
#define BK   32
#define NKC  (H / BK)

// padded SMEM row: 32 halves + 8 pad = 80 B (conflict-free for LDSM)
#define ROWB     80
#define XS_OFF   0
#define WS_HI    10240
#define WS_LO    20480
#define STAGE    30720
#define SC_OFF   (2 * STAGE)          // 61440
#define B1_OFF   (SC_OFF + 512)
#define W2_OFF   (B1_OFF + 512)
#define SMEM_TOTAL (W2_OFF + 512)     // 62976 B -> 2 CTAs/SM easily

// ---------------- scratch ----------------
__device__ float d_scores[NODES];
__device__ float d_cmax[NCHUNK];
__device__ float d_cdenom[NCHUNK];
__device__ int   d_gstart[NGRAPH + 1];
__device__ int   d_batch32[NODES];
__device__ __align__(16) __half d_W1T_hi[H * H];  // [n][k]
__device__ __align__(16) __half d_W1T_lo[H * H];  // [n][k]

// ---------------- helpers ----------------
__device__ __forceinline__ uint32_t smem_u32(const void* p) {
    uint32_t a;
    asm("{ .reg .u64 t; cvta.to.shared.u64 t, %1; cvt.u32.u64 %0, t; }"
        : "=r"(a) : "l"(p));
    return a;
}
__device__ __forceinline__ void cp_async16(uint32_t dst, const void* src) {
    asm volatile("cp.async.cg.shared.global [%0], [%1], 16;"
                 :: "r"(dst), "l"(src) : "memory");
}
__device__ __forceinline__ uint32_t f16pack(float a, float b) {
    uint32_t r;
    asm("cvt.rn.f16x2.f32 %0, %1, %2;" : "=r"(r) : "f"(b), "f"(a));
    return r;
}
__device__ __forceinline__ float fast_tanh(float x) {
    float p = fminf(fmaxf(x, -15.f), 15.f);
    float e = __expf(2.f * p);
    return __fdividef(e - 1.f, e + 1.f);
}
__device__ __forceinline__ void ldsm4(uint32_t* r, uint32_t addr) {
    asm volatile("ldmatrix.sync.aligned.m8n8.x4.shared.b16 {%0,%1,%2,%3}, [%4];"
                 : "=r"(r[0]), "=r"(r[1]), "=r"(r[2]), "=r"(r[3]) : "r"(addr));
}
#define MMA_F16(c, a0, a1, a2, a3, b0, b1)                                     \
    asm volatile(                                                              \
        "mma.sync.aligned.m16n8k16.row.col.f32.f16.f16.f32 "                   \
        "{%0,%1,%2,%3}, {%4,%5,%6,%7}, {%8,%9}, {%0,%1,%2,%3};"                \
        : "+f"(c[0]), "+f"(c[1]), "+f"(c[2]), "+f"(c[3])                       \
        : "r"(a0), "r"(a1), "r"(a2), "r"(a3), "r"(b0), "r"(b1))

// ---------------- W1 split (fp16 hi + fp16 lo) + transpose ----------------
__global__ void prep_w_kernel(const float* __restrict__ W1)
{
    int k = blockIdx.x, n = threadIdx.x;
    float v = W1[k * H + n];
    __half hi = __float2half_rn(v);
    d_W1T_hi[n * H + k] = hi;
    d_W1T_lo[n * H + k] = __float2half_rn(v - __half2float(hi));
}

// ---------------- batch -> int32, zero scores ----------------
__global__ void conv_batch_kernel(const void* __restrict__ batch)
{
    int i = blockIdx.x * blockDim.x + threadIdx.x;
    if (i >= NODES) return;
    const int* b32 = (const int*)batch;
    bool is64 = (b32[128] == 1);
    d_batch32[i] = is64 ? (int)((const long long*)batch)[i] : b32[i];
    d_scores[i] = 0.f;
}

__global__ void calc_gstart_kernel()
{
    int i = blockIdx.x * blockDim.x + threadIdx.x;
    if (i >= NODES) return;
    int b = d_batch32[i];
    if (i == 0) {
        for (int g = 0; g <= b; ++g) d_gstart[g] = 0;
    } else {
        int pb = d_batch32[i - 1];
        for (int g = pb + 1; g <= b; ++g) d_gstart[g] = i;
    }
    if (i == NODES - 1)
        for (int g = b + 1; g <= NGRAPH; ++g) d_gstart[g] = NODES;
}

// ---------------- pipelined fp16 HMMA GEMM -> tanh -> dot(W2) -> scores ----------
extern __shared__ __align__(16) char smem[];

__global__ void __launch_bounds__(256, 2) gemm_scores_kernel(
    const float* __restrict__ x, const float* __restrict__ b1,
    const float* __restrict__ W2)
{
    const int tid = threadIdx.x;
    const int warp = tid >> 5, lane = tid & 31;
    const int g = lane >> 2, t = lane & 3;
    const int warp_m = warp & 1;
    const int warp_n = warp >> 1;
    const int row0 = (blockIdx.x >> 1) * TM;
    const int cb   = blockIdx.x & 1;
    const int col_base = cb * TN;

    float* score_s = (float*)(smem + SC_OFF);
    float* b1s     = (float*)(smem + B1_OFF);
    float* w2s     = (float*)(smem + W2_OFF);
    const uint32_t sb = smem_u32(smem);

    if (tid < 128) {
        score_s[tid] = 0.f;
        b1s[tid] = b1[col_base + tid];
        w2s[tid] = W2[col_base + tid];
    }

    const int r  = tid >> 1;
    const int hf = tid & 1;

    const uint32_t lrow  = lane & 15;
    const uint32_t lhalf = (lane >> 4) * 16;
    uint32_t aBase[4], bBase[2];
#pragma unroll
    for (int mf = 0; mf < 4; ++mf)
        aBase[mf] = (uint32_t)(warp_m * 64 + mf * 16 + lrow) * ROWB + lhalf;
#pragma unroll
    for (int p = 0; p < 2; ++p)
        bBase[p] = (uint32_t)(warp_n * 32 + p * 16 + lrow) * ROWB + lhalf;

    float acc[4][4][4];
#pragma unroll
    for (int a = 0; a < 4; ++a)
#pragma unroll
        for (int b = 0; b < 4; ++b)
#pragma unroll
            for (int c = 0; c < 4; ++c) acc[a][b][c] = 0.f;

    const uint32_t doff = (uint32_t)r * ROWB + (uint32_t)hf * 32;

    // ---- prologue: fill stage 0 ----
    {
        const float4* ap = (const float4*)(x + (size_t)(row0 + r) * H + hf * 16);
        float4 av[4];
#pragma unroll
        for (int j = 0; j < 4; ++j) av[j] = ap[j];

        uint32_t hv[8];
#pragma unroll
        for (int j = 0; j < 4; ++j) {
            hv[2 * j]     = f16pack(av[j].x, av[j].y);
            hv[2 * j + 1] = f16pack(av[j].z, av[j].w);
        }
        *(uint4*)(smem + XS_OFF + doff)      = make_uint4(hv[0], hv[1], hv[2], hv[3]);
        *(uint4*)(smem + XS_OFF + doff + 16) = make_uint4(hv[4], hv[5], hv[6], hv[7]);

        const __half* gh = d_W1T_hi + (size_t)(col_base + r) * H + hf * 16;
        const __half* gl = d_W1T_lo + (size_t)(col_base + r) * H + hf * 16;
        cp_async16(sb + WS_HI + doff,      gh);
        cp_async16(sb + WS_HI + doff + 16, gh + 8);
        cp_async16(sb + WS_LO + doff,      gl);
        cp_async16(sb + WS_LO + doff + 16, gl + 8);
        asm volatile("cp.async.commit_group;" ::: "memory");
        asm volatile("cp.async.wait_group 0;" ::: "memory");
    }
    __syncthreads();

    // ---- main loop (fully unrolled) ----
#pragma unroll
    for (int kc = 0; kc < NKC; ++kc) {
        const int cur = kc & 1;
        const int nxt = cur ^ 1;
        const bool has_next = (kc + 1) < NKC;
        const uint32_t sc = sb + cur * STAGE;
        float4 av[4];

        if (has_next) {
            const int k1 = (kc + 1) * BK;
            const float4* ap =
                (const float4*)(x + (size_t)(row0 + r) * H + k1 + hf * 16);
#pragma unroll
            for (int j = 0; j < 4; ++j) av[j] = ap[j];
            const uint32_t dst = sb + nxt * STAGE;
            const __half* gh = d_W1T_hi + (size_t)(col_base + r) * H + k1 + hf * 16;
            const __half* gl = d_W1T_lo + (size_t)(col_base + r) * H + k1 + hf * 16;
            cp_async16(dst + WS_HI + doff,      gh);
            cp_async16(dst + WS_HI + doff + 16, gh + 8);
            cp_async16(dst + WS_LO + doff,      gl);
            cp_async16(dst + WS_LO + doff + 16, gl + 8);
            asm volatile("cp.async.commit_group;" ::: "memory");
        }

#pragma unroll
        for (int ks = 0; ks < 2; ++ks) {
            const uint32_t ko = (uint32_t)ks * 32;
            uint32_t BH[2][4], BL[2][4];
            ldsm4(BH[0], sc + WS_HI + bBase[0] + ko);
            ldsm4(BH[1], sc + WS_HI + bBase[1] + ko);
            ldsm4(BL[0], sc + WS_LO + bBase[0] + ko);
            ldsm4(BL[1], sc + WS_LO + bBase[1] + ko);
#pragma unroll
            for (int mf = 0; mf < 4; ++mf) {
                uint32_t AH[4];
                ldsm4(AH, sc + XS_OFF + aBase[mf] + ko);
#pragma unroll
                for (int nf = 0; nf < 4; ++nf)
                    MMA_F16(acc[mf][nf], AH[0], AH[1], AH[2], AH[3],
                            BH[nf >> 1][nf & 1], BH[nf >> 1][(nf & 1) + 2]);
#pragma unroll
                for (int nf = 0; nf < 4; ++nf)
                    MMA_F16(acc[mf][nf], AH[0], AH[1], AH[2], AH[3],
                            BL[nf >> 1][nf & 1], BL[nf >> 1][(nf & 1) + 2]);
            }
        }

        if (has_next) {
            char* stgn = smem + nxt * STAGE;
            uint32_t hv[8];
#pragma unroll
            for (int j = 0; j < 4; ++j) {
                hv[2 * j]     = f16pack(av[j].x, av[j].y);
                hv[2 * j + 1] = f16pack(av[j].z, av[j].w);
            }
            *(uint4*)(stgn + XS_OFF + doff)      = make_uint4(hv[0], hv[1], hv[2], hv[3]);
            *(uint4*)(stgn + XS_OFF + doff + 16) = make_uint4(hv[4], hv[5], hv[6], hv[7]);
            asm volatile("cp.async.wait_group 0;" ::: "memory");
        }
        __syncthreads();
    }

    // ---- epilogue ----
    float partA[4] = {0.f, 0.f, 0.f, 0.f};
    float partB[4] = {0.f, 0.f, 0.f, 0.f};
#pragma unroll
    for (int mf = 0; mf < 4; ++mf) {
#pragma unroll
        for (int nf = 0; nf < 4; ++nf) {
            const int c0 = warp_n * 32 + nf * 8 + 2 * t;
            const float w20 = w2s[c0], w21 = w2s[c0 + 1];
            const float bb0 = b1s[c0], bb1 = b1s[c0 + 1];
            partA[mf] += fast_tanh(acc[mf][nf][0] + bb0) * w20
                       + fast_tanh(acc[mf][nf][1] + bb1) * w21;
            partB[mf] += fast_tanh(acc[mf][nf][2] + bb0) * w20
                       + fast_tanh(acc[mf][nf][3] + bb1) * w21;
        }
    }
#pragma unroll
    for (int mf = 0; mf < 4; ++mf) {
        partA[mf] += __shfl_xor_sync(0xffffffffu, partA[mf], 1);
        partA[mf] += __shfl_xor_sync(0xffffffffu, partA[mf], 2);
        partB[mf] += __shfl_xor_sync(0xffffffffu, partB[mf], 1);
        partB[mf] += __shfl_xor_sync(0xffffffffu, partB[mf], 2);
    }
    if (t == 0) {
#pragma unroll
        for (int mf = 0; mf < 4; ++mf) {
            atomicAdd(&score_s[warp_m * 64 + mf * 16 + g], partA[mf]);
            atomicAdd(&score_s[warp_m * 64 + mf * 16 + g + 8], partB[mf]);
        }
    }
    __syncthreads();
    if (tid < 128) atomicAdd(&d_scores[row0 + tid], score_s[tid]);
}

// ---------------- per-chunk max + exp-sum ----------------
__global__ void chunk_stats_kernel()
{
    const int c = blockIdx.x;
    const int s = d_gstart[c * 32];
    const int e = d_gstart[c * 32 + 32];
    const int tid = threadIdx.x;

    __shared__ float red[8];
    float m = -3.4e38f;
    for (int i = s + tid; i < e; i += 256) m = fmaxf(m, d_scores[i]);
#pragma unroll
    for (int o = 16; o; o >>= 1) m = fmaxf(m, __shfl_xor_sync(0xffffffffu, m, o));
    if ((tid & 31) == 0) red[tid >> 5] = m;
    __syncthreads();
    if (tid == 0) {
        float mm = red[0];
        for (int j = 1; j < 8; ++j) mm = fmaxf(mm, red[j]);
        red[0] = mm;
    }
    __syncthreads();
    const float bm = red[0];
    __syncthreads();

    float sum = 0.f;
    for (int i = s + tid; i < e; i += 256) sum += expf(d_scores[i] - bm);
#pragma unroll
    for (int o = 16; o; o >>= 1) sum += __shfl_xor_sync(0xffffffffu, sum, o);
    if ((tid & 31) == 0) red[tid >> 5] = sum;
    __syncthreads();
    if (tid == 0) {
        float ss = 0.f;
        for (int j = 0; j < 8; ++j) ss += red[j];
        d_cmax[c] = bm;
        d_cdenom[c] = ss;
    }
}

// ---------------- weighted pooling ----------------
__global__ void pool_kernel(const float* __restrict__ x, float* __restrict__ out)
{
    const int gph = blockIdx.x;
    const int s = d_gstart[gph], e = d_gstart[gph + 1];
    const int c = gph >> 5;
    const float m = d_cmax[c];
    const float invd = (e > s) ? 1.f / d_cdenom[c] : 0.f;
    const int t = threadIdx.x;

    __shared__ float sw[256];
    float acc = 0.f;
    for (int base = s; base < e; base += 256) {
        const int cnt = min(256, e - base);
        if (t < cnt) sw[t] = expf(d_scores[base + t] - m) * invd;
        __syncthreads();
#pragma unroll 8
        for (int j = 0; j < cnt; ++j)
            acc += sw[j] * x[(size_t)(base + j) * H + t];
        __syncthreads();
    }
    out[(size_t)gph * H + t] = acc;
}

// ---------------- launch ----------------
extern "C" void kernel_launch(void* const* d_in, const int* in_sizes, int n_in,
                              void* d_out, int out_size)
{
    const float* x     = (const float*)d_in[0];
    const void*  batch = d_in[1];
    const float* W1    = (const float*)d_in[2];
    const float* b1    = (const float*)d_in[3];
    const float* W2    = (const float*)d_in[4];
    float* out = (float*)d_out;

    cudaFuncSetAttribute(gemm_scores_kernel,
                         cudaFuncAttributeMaxDynamicSharedMemorySize, SMEM_TOTAL);

    prep_w_kernel<<<H, H>>>(W1);
    conv_batch_kernel<<<NODES / 256, 256>>>(batch);
    calc_gstart_kernel<<<NODES / 256, 256>>>();
    gemm_scores_kernel<<<(NODES / TM) * 2, 256, SMEM_TOTAL>>>(x, b1, W2);
    chunk_stats_kernel<<<NCHUNK, 256>>>();
    pool_kernel<<<NGRAPH, 256>>>(x, out);
}